// round 6
// baseline (speedup 1.0000x reference)
#include <cuda_runtime.h>
#include <cuda_bf16.h>

#define N_NODES 50000
#define N_EDGES 800000
#define DIM 128
#define NBS ((N_NODES + 255) / 256)   // 196 scan blocks

// ---------------- device scratch (no allocations allowed) ----------------
__device__ float g_deg[N_NODES];
__device__ float g_dis[N_NODES];
__device__ int   g_cnt[N_NODES];
__device__ int   g_pre[N_NODES];
__device__ int   g_bsum[NBS];
__device__ int   g_boff[NBS];
__device__ int   g_rowoff[N_NODES + 1];
__device__ int   g_cursor[N_NODES];
__device__ int   g_eid[N_EDGES];
__device__ float g_h[N_NODES * DIM];
__device__ float g_t[N_NODES * DIM];

// ---------------- setup kernels ----------------
__global__ void init_kernel() {
    int i = blockIdx.x * blockDim.x + threadIdx.x;
    if (i < N_NODES) { g_deg[i] = 0.f; g_cnt[i] = 0; }
}

__global__ void count_kernel(const int* __restrict__ ei,
                             const float* __restrict__ ew) {
    int e = blockIdx.x * blockDim.x + threadIdx.x;
    if (e < N_EDGES) {
        int d = ei[N_EDGES + e];        // dst
        atomicAdd(&g_deg[d], ew[e]);
        atomicAdd(&g_cnt[d], 1);
    }
}

// inclusive block scan (blockDim must be multiple of 32, <=1024)
__device__ __forceinline__ int block_scan_incl(int v, int* ws) {
    const int lane = threadIdx.x & 31;
    const int w = threadIdx.x >> 5;
    int incl = v;
    #pragma unroll
    for (int o = 1; o < 32; o <<= 1) {
        int t = __shfl_up_sync(0xffffffffu, incl, o);
        if (lane >= o) incl += t;
    }
    if (lane == 31) ws[w] = incl;
    __syncthreads();
    if (w == 0) {
        int nw = blockDim.x >> 5;
        int s = (lane < nw) ? ws[lane] : 0;
        #pragma unroll
        for (int o = 1; o < 32; o <<= 1) {
            int t = __shfl_up_sync(0xffffffffu, s, o);
            if (lane >= o) s += t;
        }
        if (lane < nw) ws[lane] = s;
    }
    __syncthreads();
    if (w > 0) incl += ws[w - 1];
    return incl;
}

// pass 1: per-block exclusive pre-scan + block sums; fused dis = rsqrt(deg+1)
__global__ __launch_bounds__(256) void scan1_kernel() {
    __shared__ int ws[8];
    int i = blockIdx.x * 256 + threadIdx.x;
    int v = (i < N_NODES) ? g_cnt[i] : 0;
    int incl = block_scan_incl(v, ws);
    if (i < N_NODES) g_pre[i] = incl - v;
    if (threadIdx.x == 255) g_bsum[blockIdx.x] = incl;
    if (i < N_NODES) g_dis[i] = rsqrtf(g_deg[i] + 1.0f);
}

// pass 2: scan the 196 block sums (single block)
__global__ __launch_bounds__(256) void scan2_kernel() {
    __shared__ int ws[8];
    int t = threadIdx.x;
    int v = (t < NBS) ? g_bsum[t] : 0;
    int incl = block_scan_incl(v, ws);
    if (t < NBS) g_boff[t] = incl - v;
}

// pass 3: add block offsets -> rowoff / cursor
__global__ __launch_bounds__(256) void scan3_kernel() {
    int i = blockIdx.x * 256 + threadIdx.x;
    if (i < N_NODES) {
        int r = g_pre[i] + g_boff[blockIdx.x];
        g_rowoff[i] = r;
        g_cursor[i] = r;
    }
    if (i == 0) g_rowoff[N_NODES] = N_EDGES;
}

__global__ void fill_kernel(const int* __restrict__ ei) {
    int e = blockIdx.x * blockDim.x + threadIdx.x;
    if (e < N_EDGES) {
        int d = ei[N_EDGES + e];
        int pos = atomicAdd(&g_cursor[d], 1);
        g_eid[pos] = e;
    }
}

// ---------------- f32x2 helpers ----------------
__device__ __forceinline__ unsigned long long dup2(float a) {
    unsigned long long r;
    asm("mov.b64 %0, {%1, %1};" : "=l"(r) : "f"(a));
    return r;
}
__device__ __forceinline__ void fma2(unsigned long long& acc,
                                     unsigned long long a,
                                     unsigned long long b) {
    asm("fma.rn.f32x2 %0, %1, %2, %0;" : "+l"(acc) : "l"(a), "l"(b));
}

// ---------------- GEMM: C[M,128] = A[M,128] @ W[128,128] ----------------
// 256 threads, 32-row tile. Thread (wy=tid/32, lane) computes 4 rows x 4 cols,
// accumulating packed column-pairs with fma.rn.f32x2.
// A tile stored pre-duplicated (a,a) in smem -> packed multiplier is one LDS.64.
// W column-pairs are memory-adjacent -> already packed via LDG.128.
#define MT 32
__global__ __launch_bounds__(256) void gemm_kernel(const float* __restrict__ A,
                                                   const float* __restrict__ W,
                                                   float* __restrict__ C) {
    __shared__ unsigned long long sA[MT][DIM];   // 32 KB, (a,a) pairs
    const int r0 = blockIdx.x * MT;
    const int tid = threadIdx.x;
    const int lane = tid & 31;
    const int wy = tid >> 5;          // 8 row-groups of 4 rows
    const int c0 = lane * 4;

    #pragma unroll
    for (int it = 0; it < 4; it++) {
        int idx = tid + it * 256;     // float4 index, 0..1023
        int r = idx >> 5;
        int k4 = idx & 31;
        float4 v = make_float4(0.f, 0.f, 0.f, 0.f);
        if (r0 + r < N_NODES)
            v = *(const float4*)(A + (size_t)(r0 + r) * DIM + k4 * 4);
        sA[r][k4 * 4 + 0] = dup2(v.x);
        sA[r][k4 * 4 + 1] = dup2(v.y);
        sA[r][k4 * 4 + 2] = dup2(v.z);
        sA[r][k4 * 4 + 3] = dup2(v.w);
    }
    __syncthreads();

    unsigned long long acc01[4], acc23[4];
    #pragma unroll
    for (int rr = 0; rr < 4; rr++) { acc01[rr] = 0ull; acc23[rr] = 0ull; }

    #pragma unroll 4
    for (int k = 0; k < DIM; k++) {
        ulonglong2 wv = *(const ulonglong2*)(W + k * DIM + c0);  // (w0,w1),(w2,w3)
        #pragma unroll
        for (int rr = 0; rr < 4; rr++) {
            unsigned long long a = sA[wy * 4 + rr][k];           // (a,a) broadcast
            fma2(acc01[rr], a, wv.x);
            fma2(acc23[rr], a, wv.y);
        }
    }

    #pragma unroll
    for (int rr = 0; rr < 4; rr++) {
        int r = r0 + wy * 4 + rr;
        if (r < N_NODES) {
            ulonglong2 o;
            o.x = acc01[rr];
            o.y = acc23[rr];
            *(ulonglong2*)(C + (size_t)r * DIM + c0) = o;
        }
    }
}

// ---------------- aggregation: one WARP per node (proven Round-5) ----------
__global__ __launch_bounds__(256) void agg_kernel(const float* __restrict__ h,
                                                  const float* __restrict__ bias,
                                                  float* __restrict__ out,
                                                  const int* __restrict__ ei,
                                                  const float* __restrict__ ew,
                                                  int do_relu) {
    const int w = threadIdx.x >> 5;
    const int l = threadIdx.x & 31;
    const int i = blockIdx.x * 8 + w;
    if (i >= N_NODES) return;

    const float di = g_dis[i];
    const int beg = g_rowoff[i];
    const int end = g_rowoff[i + 1];

    float4 acc  = make_float4(0.f, 0.f, 0.f, 0.f);
    float4 acc2 = make_float4(0.f, 0.f, 0.f, 0.f);

    for (int base = beg; base < end; base += 32) {
        int n = end - base;
        if (n > 32) n = 32;
        int s = 0;
        float wt = 0.f;
        if (l < n) {
            int e = g_eid[base + l];
            s = ei[e];
            wt = g_dis[s] * ew[e] * di;
        }
        int j = 0;
        for (; j + 1 < n; j += 2) {
            int   s1 = __shfl_sync(0xffffffffu, s,  j);
            float w1 = __shfl_sync(0xffffffffu, wt, j);
            int   s2 = __shfl_sync(0xffffffffu, s,  j + 1);
            float w2 = __shfl_sync(0xffffffffu, wt, j + 1);
            const float4 h1 = *(const float4*)(h + (size_t)s1 * DIM + l * 4);
            const float4 h2 = *(const float4*)(h + (size_t)s2 * DIM + l * 4);
            acc.x  += h1.x * w1; acc.y  += h1.y * w1;
            acc.z  += h1.z * w1; acc.w  += h1.w * w1;
            acc2.x += h2.x * w2; acc2.y += h2.y * w2;
            acc2.z += h2.z * w2; acc2.w += h2.w * w2;
        }
        if (j < n) {
            int   s1 = __shfl_sync(0xffffffffu, s,  j);
            float w1 = __shfl_sync(0xffffffffu, wt, j);
            const float4 h1 = *(const float4*)(h + (size_t)s1 * DIM + l * 4);
            acc.x += h1.x * w1; acc.y += h1.y * w1;
            acc.z += h1.z * w1; acc.w += h1.w * w1;
        }
    }

    acc.x += acc2.x; acc.y += acc2.y; acc.z += acc2.z; acc.w += acc2.w;

    const float dd = di * di;
    const float4 hi = *(const float4*)(h + (size_t)i * DIM + l * 4);
    const float4 bv = *(const float4*)(bias + l * 4);
    acc.x += hi.x * dd + bv.x;
    acc.y += hi.y * dd + bv.y;
    acc.z += hi.z * dd + bv.z;
    acc.w += hi.w * dd + bv.w;
    if (do_relu) {
        acc.x = fmaxf(acc.x, 0.f);
        acc.y = fmaxf(acc.y, 0.f);
        acc.z = fmaxf(acc.z, 0.f);
        acc.w = fmaxf(acc.w, 0.f);
    }
    *(float4*)(out + (size_t)i * DIM + l * 4) = acc;
}

// ---------------- launch ----------------
extern "C" void kernel_launch(void* const* d_in, const int* in_sizes, int n_in,
                              void* d_out, int out_size) {
    const float* x  = (const float*)d_in[0];
    const int*   ei = (const int*)d_in[1];
    const float* ew = (const float*)d_in[2];
    const float* W1 = (const float*)d_in[3];
    const float* b1 = (const float*)d_in[4];
    const float* W2 = (const float*)d_in[5];
    const float* b2 = (const float*)d_in[6];
    float* out = (float*)d_out;

    float* h_buf; cudaGetSymbolAddress((void**)&h_buf, g_h);
    float* t_buf; cudaGetSymbolAddress((void**)&t_buf, g_t);

    const int NB_N = (N_NODES + 255) / 256;
    const int NB_E = (N_EDGES + 255) / 256;
    const int NB_G = (N_NODES + MT - 1) / MT;
    const int NB_A = (N_NODES + 7) / 8;

    // graph structure setup
    init_kernel<<<NB_N, 256>>>();
    count_kernel<<<NB_E, 256>>>(ei, ew);
    scan1_kernel<<<NBS, 256>>>();      // also computes g_dis
    scan2_kernel<<<1, 256>>>();
    scan3_kernel<<<NBS, 256>>>();
    fill_kernel<<<NB_E, 256>>>(ei);

    // layer 1
    gemm_kernel<<<NB_G, 256>>>(x, W1, h_buf);
    agg_kernel<<<NB_A, 256>>>(h_buf, b1, t_buf, ei, ew, 1);

    // layer 2
    gemm_kernel<<<NB_G, 256>>>(t_buf, W2, h_buf);
    agg_kernel<<<NB_A, 256>>>(h_buf, b2, out, ei, ew, 0);
}

// round 8
// speedup vs baseline: 1.7051x; 1.7051x over previous
#include <cuda_runtime.h>
#include <cuda_bf16.h>
#include <cstdint>

#define N_NODES 50000
#define N_EDGES 800000
#define DIM 128
#define NBS ((N_NODES + 255) / 256)   // 196 scan blocks

// ---------------- device scratch (no allocations allowed) ----------------
__device__ float g_deg[N_NODES];
__device__ float g_dis[N_NODES];
__device__ int   g_cnt[N_NODES];
__device__ int   g_pre[N_NODES];
__device__ int   g_bsum[NBS];
__device__ int   g_boff[NBS];
__device__ int   g_rowoff[N_NODES + 1];
__device__ int   g_cursor[N_NODES];
__device__ int   g_eid[N_EDGES];
__device__ float g_h[N_NODES * DIM];
__device__ float g_t[N_NODES * DIM];

// ---------------- setup kernels ----------------
__global__ void init_kernel() {
    int i = blockIdx.x * blockDim.x + threadIdx.x;
    if (i < N_NODES) { g_deg[i] = 0.f; g_cnt[i] = 0; }
}

__global__ void count_kernel(const int* __restrict__ ei,
                             const float* __restrict__ ew) {
    int e = blockIdx.x * blockDim.x + threadIdx.x;
    if (e < N_EDGES) {
        int d = ei[N_EDGES + e];        // dst
        atomicAdd(&g_deg[d], ew[e]);
        atomicAdd(&g_cnt[d], 1);
    }
}

__device__ __forceinline__ int block_scan_incl(int v, int* ws) {
    const int lane = threadIdx.x & 31;
    const int w = threadIdx.x >> 5;
    int incl = v;
    #pragma unroll
    for (int o = 1; o < 32; o <<= 1) {
        int t = __shfl_up_sync(0xffffffffu, incl, o);
        if (lane >= o) incl += t;
    }
    if (lane == 31) ws[w] = incl;
    __syncthreads();
    if (w == 0) {
        int nw = blockDim.x >> 5;
        int s = (lane < nw) ? ws[lane] : 0;
        #pragma unroll
        for (int o = 1; o < 32; o <<= 1) {
            int t = __shfl_up_sync(0xffffffffu, s, o);
            if (lane >= o) s += t;
        }
        if (lane < nw) ws[lane] = s;
    }
    __syncthreads();
    if (w > 0) incl += ws[w - 1];
    return incl;
}

__global__ __launch_bounds__(256) void scan1_kernel() {
    __shared__ int ws[8];
    int i = blockIdx.x * 256 + threadIdx.x;
    int v = (i < N_NODES) ? g_cnt[i] : 0;
    int incl = block_scan_incl(v, ws);
    if (i < N_NODES) g_pre[i] = incl - v;
    if (threadIdx.x == 255) g_bsum[blockIdx.x] = incl;
    if (i < N_NODES) g_dis[i] = rsqrtf(g_deg[i] + 1.0f);
}

__global__ __launch_bounds__(256) void scan2_kernel() {
    __shared__ int ws[8];
    int t = threadIdx.x;
    int v = (t < NBS) ? g_bsum[t] : 0;
    int incl = block_scan_incl(v, ws);
    if (t < NBS) g_boff[t] = incl - v;
}

__global__ __launch_bounds__(256) void scan3_kernel() {
    int i = blockIdx.x * 256 + threadIdx.x;
    if (i < N_NODES) {
        int r = g_pre[i] + g_boff[blockIdx.x];
        g_rowoff[i] = r;
        g_cursor[i] = r;
    }
    if (i == 0) g_rowoff[N_NODES] = N_EDGES;
}

__global__ void fill_kernel(const int* __restrict__ ei) {
    int e = blockIdx.x * blockDim.x + threadIdx.x;
    if (e < N_EDGES) {
        int d = ei[N_EDGES + e];
        int pos = atomicAdd(&g_cursor[d], 1);
        g_eid[pos] = e;
    }
}

// ---------------- tf32 helpers ----------------
__device__ __forceinline__ uint32_t f2tf32(float f) {
    uint32_t r;
    asm("cvt.rna.tf32.f32 %0, %1;" : "=r"(r) : "f"(f));
    return r;
}
__device__ __forceinline__ void mma_tf32(float& c0, float& c1, float& c2, float& c3,
                                         uint32_t a0, uint32_t a1, uint32_t a2, uint32_t a3,
                                         uint32_t b0, uint32_t b1) {
    asm volatile(
        "mma.sync.aligned.m16n8k8.row.col.f32.tf32.tf32.f32 "
        "{%0,%1,%2,%3}, {%4,%5,%6,%7}, {%8,%9}, {%0,%1,%2,%3};"
        : "+f"(c0), "+f"(c1), "+f"(c2), "+f"(c3)
        : "r"(a0), "r"(a1), "r"(a2), "r"(a3), "r"(b0), "r"(b1));
}

// ---------------- GEMM: C[128-tile,128] = A @ W  (tf32 mma.sync) ------------
// 8 warps; warp w computes rows [w*16, w*16+16) x all 128 cols.
// smem: sA[128][132] tf32, sW[128][132] tf32 (pitch 132 words for bank spread).
#define PITCH 132
#define SM_WORDS (2 * DIM * PITCH)      // 33792 words = 135168 B
__global__ __launch_bounds__(256) void gemm_tc_kernel(const float* __restrict__ A,
                                                      const float* __restrict__ W,
                                                      float* __restrict__ C) {
    extern __shared__ uint32_t smem[];
    uint32_t* sA = smem;
    uint32_t* sW = smem + DIM * PITCH;
    const int tid = threadIdx.x;
    const int wid = tid >> 5;
    const int lane = tid & 31;
    const int g = lane >> 2;            // group 0..7
    const int tg = lane & 3;            // thread-in-group 0..3
    const int r0 = blockIdx.x * 128;

    // stage A tile (guarded) and W, converting to tf32
    #pragma unroll
    for (int it = 0; it < 16; it++) {
        int idx = tid + it * 256;       // float4 idx 0..4095
        int r = idx >> 5;
        int c4 = idx & 31;
        float4 av = make_float4(0.f, 0.f, 0.f, 0.f);
        if (r0 + r < N_NODES)
            av = *(const float4*)(A + (size_t)(r0 + r) * DIM + c4 * 4);
        uint32_t* pa = sA + r * PITCH + c4 * 4;
        pa[0] = f2tf32(av.x); pa[1] = f2tf32(av.y);
        pa[2] = f2tf32(av.z); pa[3] = f2tf32(av.w);
        float4 wv = *(const float4*)(W + r * DIM + c4 * 4);
        uint32_t* pw = sW + r * PITCH + c4 * 4;
        pw[0] = f2tf32(wv.x); pw[1] = f2tf32(wv.y);
        pw[2] = f2tf32(wv.z); pw[3] = f2tf32(wv.w);
    }
    __syncthreads();

    float acc[16][4];
    #pragma unroll
    for (int nt = 0; nt < 16; nt++)
        #pragma unroll
        for (int q = 0; q < 4; q++) acc[nt][q] = 0.f;

    const uint32_t* aBase = sA + (wid * 16 + g) * PITCH;

    for (int ks = 0; ks < 16; ks++) {
        const int k0 = ks * 8;
        uint32_t a0 = aBase[k0 + tg];
        uint32_t a1 = aBase[8 * PITCH + k0 + tg];
        uint32_t a2 = aBase[k0 + tg + 4];
        uint32_t a3 = aBase[8 * PITCH + k0 + tg + 4];
        const uint32_t* b0p = sW + (k0 + tg) * PITCH + g;
        const uint32_t* b1p = sW + (k0 + tg + 4) * PITCH + g;
        #pragma unroll
        for (int nt = 0; nt < 16; nt++) {
            uint32_t b0 = b0p[nt * 8];
            uint32_t b1 = b1p[nt * 8];
            mma_tf32(acc[nt][0], acc[nt][1], acc[nt][2], acc[nt][3],
                     a0, a1, a2, a3, b0, b1);
        }
    }

    // epilogue: C[row][n0 + 2tg .. +1] from fragments
    const int row0 = r0 + wid * 16 + g;
    const int row1 = row0 + 8;
    #pragma unroll
    for (int nt = 0; nt < 16; nt++) {
        int c = nt * 8 + tg * 2;
        if (row0 < N_NODES)
            *(float2*)(C + (size_t)row0 * DIM + c) = make_float2(acc[nt][0], acc[nt][1]);
        if (row1 < N_NODES)
            *(float2*)(C + (size_t)row1 * DIM + c) = make_float2(acc[nt][2], acc[nt][3]);
    }
}

// ---------------- aggregation: one WARP per node (proven Round-5) ----------
__global__ __launch_bounds__(256) void agg_kernel(const float* __restrict__ h,
                                                  const float* __restrict__ bias,
                                                  float* __restrict__ out,
                                                  const int* __restrict__ ei,
                                                  const float* __restrict__ ew,
                                                  int do_relu) {
    const int w = threadIdx.x >> 5;
    const int l = threadIdx.x & 31;
    const int i = blockIdx.x * 8 + w;
    if (i >= N_NODES) return;

    const float di = g_dis[i];
    const int beg = g_rowoff[i];
    const int end = g_rowoff[i + 1];

    float4 acc  = make_float4(0.f, 0.f, 0.f, 0.f);
    float4 acc2 = make_float4(0.f, 0.f, 0.f, 0.f);

    for (int base = beg; base < end; base += 32) {
        int n = end - base;
        if (n > 32) n = 32;
        int s = 0;
        float wt = 0.f;
        if (l < n) {
            int e = g_eid[base + l];
            s = ei[e];
            wt = g_dis[s] * ew[e] * di;
        }
        int j = 0;
        for (; j + 1 < n; j += 2) {
            int   s1 = __shfl_sync(0xffffffffu, s,  j);
            float w1 = __shfl_sync(0xffffffffu, wt, j);
            int   s2 = __shfl_sync(0xffffffffu, s,  j + 1);
            float w2 = __shfl_sync(0xffffffffu, wt, j + 1);
            const float4 h1 = *(const float4*)(h + (size_t)s1 * DIM + l * 4);
            const float4 h2 = *(const float4*)(h + (size_t)s2 * DIM + l * 4);
            acc.x  += h1.x * w1; acc.y  += h1.y * w1;
            acc.z  += h1.z * w1; acc.w  += h1.w * w1;
            acc2.x += h2.x * w2; acc2.y += h2.y * w2;
            acc2.z += h2.z * w2; acc2.w += h2.w * w2;
        }
        if (j < n) {
            int   s1 = __shfl_sync(0xffffffffu, s,  j);
            float w1 = __shfl_sync(0xffffffffu, wt, j);
            const float4 h1 = *(const float4*)(h + (size_t)s1 * DIM + l * 4);
            acc.x += h1.x * w1; acc.y += h1.y * w1;
            acc.z += h1.z * w1; acc.w += h1.w * w1;
        }
    }

    acc.x += acc2.x; acc.y += acc2.y; acc.z += acc2.z; acc.w += acc2.w;

    const float dd = di * di;
    const float4 hi = *(const float4*)(h + (size_t)i * DIM + l * 4);
    const float4 bv = *(const float4*)(bias + l * 4);
    acc.x += hi.x * dd + bv.x;
    acc.y += hi.y * dd + bv.y;
    acc.z += hi.z * dd + bv.z;
    acc.w += hi.w * dd + bv.w;
    if (do_relu) {
        acc.x = fmaxf(acc.x, 0.f);
        acc.y = fmaxf(acc.y, 0.f);
        acc.z = fmaxf(acc.z, 0.f);
        acc.w = fmaxf(acc.w, 0.f);
    }
    *(float4*)(out + (size_t)i * DIM + l * 4) = acc;
}

// ---------------- launch ----------------
extern "C" void kernel_launch(void* const* d_in, const int* in_sizes, int n_in,
                              void* d_out, int out_size) {
    const float* x  = (const float*)d_in[0];
    const int*   ei = (const int*)d_in[1];
    const float* ew = (const float*)d_in[2];
    const float* W1 = (const float*)d_in[3];
    const float* b1 = (const float*)d_in[4];
    const float* W2 = (const float*)d_in[5];
    const float* b2 = (const float*)d_in[6];
    float* out = (float*)d_out;

    float* h_buf; cudaGetSymbolAddress((void**)&h_buf, g_h);
    float* t_buf; cudaGetSymbolAddress((void**)&t_buf, g_t);

    cudaFuncSetAttribute(gemm_tc_kernel,
                         cudaFuncAttributeMaxDynamicSharedMemorySize,
                         SM_WORDS * 4);

    const int NB_N = (N_NODES + 255) / 256;
    const int NB_E = (N_EDGES + 255) / 256;
    const int NB_G = (N_NODES + 127) / 128;
    const int NB_A = (N_NODES + 7) / 8;

    // graph structure setup
    init_kernel<<<NB_N, 256>>>();
    count_kernel<<<NB_E, 256>>>(ei, ew);
    scan1_kernel<<<NBS, 256>>>();      // also computes g_dis
    scan2_kernel<<<1, 256>>>();
    scan3_kernel<<<NBS, 256>>>();
    fill_kernel<<<NB_E, 256>>>(ei);

    // layer 1
    gemm_tc_kernel<<<NB_G, 256, SM_WORDS * 4>>>(x, W1, h_buf);
    agg_kernel<<<NB_A, 256>>>(h_buf, b1, t_buf, ei, ew, 1);

    // layer 2
    gemm_tc_kernel<<<NB_G, 256, SM_WORDS * 4>>>(t_buf, W2, h_buf);
    agg_kernel<<<NB_A, 256>>>(h_buf, b2, out, ei, ew, 0);
}